// round 16
// baseline (speedup 1.0000x reference)
#include <cuda_runtime.h>
#include <cuda_fp16.h>
#include <cstdint>

#define BATCH 16
#define CC 512
#define HW 1024
#define G 32
#define CG 16
#define EPS 1e-5f

#define NCHUNK 4
#define CB (BATCH / NCHUNK)   // 4 batches per chunk

typedef __half fp16;

// Split + combo encoding: x ~ h + l (fp16 hi/lo), c = fl16(h + 64*l).
// GEMM computes D = acc1 + (acc2-acc1)/64 with acc1=Ah*Bh, acc2=Ac*Bc,
// recovering Ah*Bh + Ah*Bl + Al*Bh + 64*Al*Bl (error ~2^-18).
#define LAM 64.f
#define LAMINV 0.015625f

// ---------------------------------------------------------------------------
// Scratch (device globals)
// ---------------------------------------------------------------------------
__device__ float g_stats[BATCH * G * 2];
__device__ __align__(16) fp16 g_ht_hi[BATCH * HW * CC], g_ht_c[BATCH * HW * CC];
__device__ __align__(16) fp16 g_t_hi[BATCH * HW * CC],  g_t_c[BATCH * HW * CC];
__device__ __align__(16) fp16 g_ve_hi[BATCH * CC * HW], g_ve_c[BATCH * CC * HW];
__device__ __align__(16) float g_s[(size_t)BATCH * HW * HW];
__device__ __align__(16) fp16 g_p_hi[(size_t)BATCH * HW * HW];
__device__ __align__(16) fp16 g_p_c[(size_t)BATCH * HW * HW];
__device__ __align__(16) fp16 g_wqT_hi[CC * CC], g_wqT_c[CC * CC];
__device__ __align__(16) fp16 g_wkT_hi[CC * CC], g_wkT_c[CC * CC];
__device__ __align__(16) fp16 g_wvT_hi[CC * CC], g_wvT_c[CC * CC];
__device__ __align__(16) fp16 g_wp_hi[CC * CC],  g_wp_c[CC * CC];
__device__ __align__(16) fp16 g_m2_hi[CC * CC],  g_m2_c[CC * CC];
__device__ __align__(16) fp16 g_wpv_hi[CC * CC], g_wpv_c[CC * CC];
__device__ float g_u[CC], g_vbp[CC];

// ---------------------------------------------------------------------------
// Streams + events (created once at load; no device-memory allocation).
// ---------------------------------------------------------------------------
namespace {
struct AuxStreams {
    cudaStream_t sc[NCHUNK - 1] = {};
    cudaStream_t sw = nullptr;
    cudaEvent_t e_fork = nullptr, e_wp = nullptr;
    cudaEvent_t e_done[NCHUNK - 1] = {};
    AuxStreams() {
        for (int i = 0; i < NCHUNK - 1; i++) {
            cudaStreamCreateWithFlags(&sc[i], cudaStreamNonBlocking);
            cudaEventCreateWithFlags(&e_done[i], cudaEventDisableTiming);
        }
        cudaStreamCreateWithFlags(&sw, cudaStreamNonBlocking);
        cudaEventCreateWithFlags(&e_fork, cudaEventDisableTiming);
        cudaEventCreateWithFlags(&e_wp, cudaEventDisableTiming);
    }
};
AuxStreams g_aux;
}  // namespace

// ---------------------------------------------------------------------------
// PTX helpers
// ---------------------------------------------------------------------------
__device__ __forceinline__ uint32_t smem_u32(const void* p) {
    uint32_t a;
    asm("{ .reg .u64 t; cvta.to.shared.u64 t, %1; cvt.u32.u64 %0, t; }"
        : "=r"(a) : "l"(p));
    return a;
}
__device__ __forceinline__ void cpa16(uint32_t dst, const void* src) {
    asm volatile("cp.async.ca.shared.global [%0], [%1], 16;"
                 :: "r"(dst), "l"(src));
}
#define CP_COMMIT() asm volatile("cp.async.commit_group;" ::: "memory")
#define CP_WAIT1() asm volatile("cp.async.wait_group 1;" ::: "memory")

__device__ __forceinline__ void ldsm_x4(uint32_t* r, uint32_t addr) {
    asm volatile(
        "ldmatrix.sync.aligned.m8n8.x4.shared.b16 {%0,%1,%2,%3}, [%4];"
        : "=r"(r[0]), "=r"(r[1]), "=r"(r[2]), "=r"(r[3]) : "r"(addr));
}
__device__ __forceinline__ void mma16816(float* c, const uint32_t* a,
                                         const uint32_t* b) {
    asm volatile(
        "mma.sync.aligned.m16n8k16.row.col.f32.f16.f16.f32 "
        "{%0,%1,%2,%3}, {%4,%5,%6,%7}, {%8,%9}, {%0,%1,%2,%3};"
        : "+f"(c[0]), "+f"(c[1]), "+f"(c[2]), "+f"(c[3])
        : "r"(a[0]), "r"(a[1]), "r"(a[2]), "r"(a[3]), "r"(b[0]), "r"(b[1]));
}

// split fp32 -> (hi, combo) fp16 pair
__device__ __forceinline__ void split_hc(float v, fp16& h, fp16& c) {
    h = __float2half(v);
    float hf = __half2float(h);
    fp16 l = __float2half(v - hf);
    c = __float2half(hf + LAM * __half2float(l));
}

// Swizzled 64B-row layout: conflict-free for ldmatrix + cp.async
#define SWZ(row, kb) \
    ((uint32_t)(row) * 64u + (((((uint32_t)(kb)) >> 4) ^ (((uint32_t)(row) >> 1) & 3u)) << 4))

#define MATB 8192u           // 128 rows * 64 B
#define NSTAGE 3
#define SMEM_T3 (NSTAGE * 4 * MATB)   // 98304: Ah, Ac, Bh, Bc

// ---------------------------------------------------------------------------
// 2-MMA compensated split-fp16 GEMM: D[m][n] = sum_k A[m][k]*B[n][k]
// acc1 += Ah*Bh ; acc2 += Ac*Bc ; D = acc1 + (acc2-acc1)/64 (fp32-grade).
// 128x128 CTA tile, BK=32, 256 thr (8 warps, 32x64 warp tiles), 3-stage.
// MODE 0: +bias[n], fp16 h/c out
// MODE 1: +bias[m], fp16 h/c out
// MODE 2: *scale,   f32 out
// MODE 3: plain,    fp16 h/c out
// MODE 4: +bias[m]+resid, f32 out
// ---------------------------------------------------------------------------
template <int MODE>
__global__ void __launch_bounds__(256, 1)
gemm_mma(const fp16* __restrict__ Ahi, const fp16* __restrict__ Acb, size_t sA,
         const fp16* __restrict__ Bhi, const fp16* __restrict__ Bcb, size_t sB,
         int K, const float* __restrict__ bias, float scale,
         const float* __restrict__ resid,
         fp16* __restrict__ Ohi, fp16* __restrict__ Ocb, float* __restrict__ Of,
         int ldO, size_t sO) {
    extern __shared__ char smem[];
    const uint32_t sb = smem_u32(smem);
    constexpr uint32_t STB = 4 * MATB;

    const int t = threadIdx.x;
    const int w = t >> 5, lane = t & 31;
    const int g = lane >> 2, tg = lane & 3;
    const int wm = (w >> 1) * 32, wn = (w & 1) * 64;
    const int bz = blockIdx.z;
    const int n0 = blockIdx.x * 128, m0 = blockIdx.y * 128;

    const fp16* arh = Ahi + bz * sA + (size_t)m0 * K;
    const fp16* arc = Acb + bz * sA + (size_t)m0 * K;
    const fp16* brh = Bhi + bz * sB + (size_t)n0 * K;
    const fp16* brc = Bcb + bz * sB + (size_t)n0 * K;

    float acc1[2][8][4], acc2[2][8][4];
#pragma unroll
    for (int i = 0; i < 2; i++)
#pragma unroll
        for (int j = 0; j < 8; j++)
#pragma unroll
            for (int e = 0; e < 4; e++) { acc1[i][j][e] = 0.f; acc2[i][j][e] = 0.f; }

    const int rbase = t >> 2, seg = t & 3;   // 64 rows x 4 segs = 256 threads

    const uint32_t a_row = (uint32_t)(wm + ((lane >> 3) & 1) * 8 + (lane & 7));
    const uint32_t a_kb = ((lane >> 4) & 1) * 16;
    const uint32_t b_row = (uint32_t)(wn + ((lane >> 4) & 1) * 8 + (lane & 7));
    const uint32_t b_kb = ((lane >> 3) & 1) * 16;

    const int nsteps = K >> 5;

    auto issue = [&](int s) {
        int kc = s << 5;
        uint32_t b0 = sb + (uint32_t)(s % NSTAGE) * STB;
#pragma unroll
        for (int j = 0; j < 2; j++) {
            int r = rbase + 64 * j;
            uint32_t so = SWZ(r, seg * 16);
            size_t go = (size_t)r * K + kc + seg * 8;
            cpa16(b0 + so, arh + go);
            cpa16(b0 + MATB + so, arc + go);
            cpa16(b0 + 2 * MATB + so, brh + go);
            cpa16(b0 + 3 * MATB + so, brc + go);
        }
        CP_COMMIT();
    };

    issue(0);
    issue(1);

    for (int s = 0; s < nsteps; s++) {
        CP_WAIT1();
        __syncthreads();
        if (s + 2 < nsteps) issue(s + 2);

        uint32_t stg = sb + (uint32_t)(s % NSTAGE) * STB;
        uint32_t pAh = stg, pAc = stg + MATB;
        uint32_t pBh = stg + 2 * MATB, pBc = stg + 3 * MATB;
#pragma unroll
        for (int kk = 0; kk < 2; kk++) {
            uint32_t kb = (uint32_t)kk * 32;
            uint32_t Ah[2][4], Ac[2][4];
#pragma unroll
            for (int mf = 0; mf < 2; mf++) {
                uint32_t ad = SWZ(a_row + mf * 16, kb + a_kb);
                ldsm_x4(Ah[mf], pAh + ad);
                ldsm_x4(Ac[mf], pAc + ad);
            }
#pragma unroll
            for (int p = 0; p < 4; p++) {
                uint32_t bd = SWZ(b_row + p * 16, kb + b_kb);
                uint32_t Bh[4], Bc[4];
                ldsm_x4(Bh, pBh + bd);
                ldsm_x4(Bc, pBc + bd);
#pragma unroll
                for (int mf = 0; mf < 2; mf++) {
                    mma16816(acc1[mf][2 * p], Ah[mf], Bh);
                    mma16816(acc2[mf][2 * p], Ac[mf], Bc);
                    mma16816(acc1[mf][2 * p + 1], Ah[mf], Bh + 2);
                    mma16816(acc2[mf][2 * p + 1], Ac[mf], Bc + 2);
                }
            }
        }
        __syncthreads();
    }

    // ---- epilogue: combine, direct row-major [m][n] store -----------------
#pragma unroll
    for (int mf = 0; mf < 2; mf++) {
        int mA = m0 + wm + mf * 16 + g;
        int mB = mA + 8;
        float bmA = 0.f, bmB = 0.f;
        if (MODE == 1 || MODE == 4) { bmA = bias[mA]; bmB = bias[mB]; }
#pragma unroll
        for (int nf = 0; nf < 8; nf++) {
            int n = n0 + wn + nf * 8 + tg * 2;
            float v0 = acc1[mf][nf][0] + LAMINV * (acc2[mf][nf][0] - acc1[mf][nf][0]);
            float v1 = acc1[mf][nf][1] + LAMINV * (acc2[mf][nf][1] - acc1[mf][nf][1]);
            float v2 = acc1[mf][nf][2] + LAMINV * (acc2[mf][nf][2] - acc1[mf][nf][2]);
            float v3 = acc1[mf][nf][3] + LAMINV * (acc2[mf][nf][3] - acc1[mf][nf][3]);
            if (MODE == 0) {
                float bn0 = bias[n], bn1 = bias[n + 1];
                v0 += bn0; v1 += bn1; v2 += bn0; v3 += bn1;
            }
            if (MODE == 1 || MODE == 4) { v0 += bmA; v1 += bmA; v2 += bmB; v3 += bmB; }
            if (MODE == 2) { v0 *= scale; v1 *= scale; v2 *= scale; v3 *= scale; }
            size_t iA = bz * sO + (size_t)mA * ldO + n;
            size_t iB = bz * sO + (size_t)mB * ldO + n;
            if (MODE == 4) {
                v0 += resid[iA]; v1 += resid[iA + 1];
                v2 += resid[iB]; v3 += resid[iB + 1];
            }
            if (MODE == 2 || MODE == 4) {
                *(float2*)&Of[iA] = make_float2(v0, v1);
                *(float2*)&Of[iB] = make_float2(v2, v3);
            } else {
                fp16 h0, c0, h1, c1, h2, c2, h3, c3;
                split_hc(v0, h0, c0); split_hc(v1, h1, c1);
                split_hc(v2, h2, c2); split_hc(v3, h3, c3);
                __half2 hA; hA.x = h0; hA.y = h1;
                __half2 hB; hB.x = h2; hB.y = h3;
                __half2 cA; cA.x = c0; cA.y = c1;
                __half2 cB; cB.x = c2; cB.y = c3;
                *(__half2*)&Ohi[iA] = hA;
                *(__half2*)&Ohi[iB] = hB;
                *(__half2*)&Ocb[iA] = cA;
                *(__half2*)&Ocb[iB] = cB;
            }
        }
    }
}

// ---------------------------------------------------------------------------
// GroupNorm stats (per-chunk)
// ---------------------------------------------------------------------------
__global__ void gn_stats(const float* __restrict__ x, int b0) {
    int bg = blockIdx.x + b0 * G;
    int bb = bg / G, g = bg % G;
    const float* xp = x + ((size_t)bb * CC + (size_t)g * CG) * HW;
    const int n = CG * HW;

    float s = 0.f, ss = 0.f;
    for (int i = threadIdx.x; i < n; i += blockDim.x) {
        float v = xp[i];
        s += v;
        ss += v * v;
    }
    __shared__ float sh0[256], sh1[256];
    sh0[threadIdx.x] = s;
    sh1[threadIdx.x] = ss;
    __syncthreads();
    for (int o = 128; o > 0; o >>= 1) {
        if (threadIdx.x < o) {
            sh0[threadIdx.x] += sh0[threadIdx.x + o];
            sh1[threadIdx.x] += sh1[threadIdx.x + o];
        }
        __syncthreads();
    }
    if (threadIdx.x == 0) {
        float mu = sh0[0] / n;
        float var = sh1[0] / n - mu * mu;
        g_stats[bg * 2] = mu;
        g_stats[bg * 2 + 1] = rsqrtf(var + EPS);
    }
}

// GroupNorm apply + transpose: x[b][c][i] -> Ht[b][i][c] fp16 h/c (per-chunk)
__global__ void gn_transpose(const float* __restrict__ x,
                             const float* __restrict__ gw,
                             const float* __restrict__ gb, int b0) {
    __shared__ float tile[32][33];
    int bz = blockIdx.z + b0;
    int i0 = blockIdx.x * 32, c0 = blockIdx.y * 32;
    int tx = threadIdx.x, ty = threadIdx.y;
    const float* xb = x + (size_t)bz * CC * HW;
#pragma unroll
    for (int r = 0; r < 4; r++) {
        int c = c0 + ty + r * 8;
        float mu = g_stats[(bz * G + (c >> 4)) * 2];
        float ri = g_stats[(bz * G + (c >> 4)) * 2 + 1];
        float v = xb[(size_t)c * HW + i0 + tx];
        tile[ty + r * 8][tx] = (v - mu) * ri * gw[c] + gb[c];
    }
    __syncthreads();
    size_t ob = (size_t)bz * HW * CC;
#pragma unroll
    for (int r = 0; r < 4; r++) {
        int i = i0 + ty + r * 8;
        float v = tile[tx][ty + r * 8];
        fp16 h, c;
        split_hc(v, h, c);
        size_t idx = ob + (size_t)i * CC + c0 + tx;
        g_ht_hi[idx] = h;
        g_ht_c[idx] = c;
    }
}

// Transpose+split 3 weight matrices: out[z][a][d] = w_z[d][a] as fp16 h/c
__global__ void wtransT(const float* __restrict__ w0, const float* __restrict__ w1,
                        const float* __restrict__ w2) {
    __shared__ float tile[32][33];
    int z = blockIdx.z;
    const float* w = z == 0 ? w0 : z == 1 ? w1 : w2;
    fp16* ohi = z == 0 ? g_wqT_hi : z == 1 ? g_wkT_hi : g_wvT_hi;
    fp16* oc = z == 0 ? g_wqT_c : z == 1 ? g_wkT_c : g_wvT_c;
    int d0 = blockIdx.x * 32, a0 = blockIdx.y * 32;
    int tx = threadIdx.x, ty = threadIdx.y;
#pragma unroll
    for (int r = 0; r < 4; r++)
        tile[ty + r * 8][tx] = w[(size_t)(d0 + ty + r * 8) * CC + a0 + tx];
    __syncthreads();
#pragma unroll
    for (int r = 0; r < 4; r++) {
        int a = a0 + ty + r * 8;
        float v = tile[tx][ty + r * 8];
        fp16 h, c;
        split_hc(v, h, c);
        size_t idx = (size_t)a * CC + d0 + tx;
        ohi[idx] = h;
        oc[idx] = c;
    }
}

// Straight split of Wp
__global__ void wsplit(const float* __restrict__ w) {
    int i = blockIdx.x * blockDim.x + threadIdx.x;
    fp16 h, c;
    split_hc(w[i], h, c);
    g_wp_hi[i] = h;
    g_wp_c[i] = c;
}

// u[b] = sum_d qb[d]*Wk[d][b]
__global__ void ubias(const float* __restrict__ qb, const float* __restrict__ wk) {
    int b = blockIdx.x * blockDim.x + threadIdx.x;
    float s = 0.f;
    for (int d = 0; d < CC; d++) s += qb[d] * wk[(size_t)d * CC + b];
    g_u[b] = s;
}

// vbp[d] = sum_c Wp[d][c]*vb[c]
__global__ void vbias(const float* __restrict__ wp, const float* __restrict__ vb) {
    int d = blockIdx.x;
    float s = 0.f;
    for (int c = threadIdx.x; c < CC; c += blockDim.x)
        s += wp[(size_t)d * CC + c] * vb[c];
    __shared__ float sh[256];
    sh[threadIdx.x] = s;
    __syncthreads();
    for (int o = 128; o > 0; o >>= 1) {
        if (threadIdx.x < o) sh[threadIdx.x] += sh[threadIdx.x + o];
        __syncthreads();
    }
    if (threadIdx.x == 0) g_vbp[d] = sh[0];
}

// Row softmax over 1024 columns; writes P as fp16 h/c
__global__ void softmax_kernel(const float* __restrict__ S,
                               fp16* __restrict__ Ph, fp16* __restrict__ Pc) {
    const float* row = S + (size_t)blockIdx.x * HW;
    int t = threadIdx.x;
    float4 v = ((const float4*)row)[t];

    __shared__ float sh[256];
    float m = fmaxf(fmaxf(v.x, v.y), fmaxf(v.z, v.w));
    sh[t] = m;
    __syncthreads();
    for (int o = 128; o > 0; o >>= 1) {
        if (t < o) sh[t] = fmaxf(sh[t], sh[t + o]);
        __syncthreads();
    }
    m = sh[0];
    __syncthreads();

    v.x = __expf(v.x - m); v.y = __expf(v.y - m);
    v.z = __expf(v.z - m); v.w = __expf(v.w - m);
    sh[t] = v.x + v.y + v.z + v.w;
    __syncthreads();
    for (int o = 128; o > 0; o >>= 1) {
        if (t < o) sh[t] += sh[t + o];
        __syncthreads();
    }
    float inv = 1.0f / sh[0];
    float p[4] = {v.x * inv, v.y * inv, v.z * inv, v.w * inv};
    size_t base = (size_t)blockIdx.x * HW + t * 4;
#pragma unroll
    for (int e = 0; e < 4; e++) {
        fp16 h, c;
        split_hc(p[e], h, c);
        Ph[base + e] = h;
        Pc[base + e] = c;
    }
}

// ---------------------------------------------------------------------------
extern "C" void kernel_launch(void* const* d_in, const int* in_sizes, int n_in,
                              void* d_out, int out_size) {
    const float* x    = (const float*)d_in[0];
    const float* gn_w = (const float*)d_in[2];
    const float* gn_b = (const float*)d_in[3];
    const float* q_w  = (const float*)d_in[4];
    const float* q_b  = (const float*)d_in[5];
    const float* k_w  = (const float*)d_in[6];
    const float* v_w  = (const float*)d_in[8];
    const float* v_b  = (const float*)d_in[9];
    const float* p_w  = (const float*)d_in[10];
    const float* p_b  = (const float*)d_in[11];
    float* out = (float*)d_out;

    fp16 *ht_hi, *ht_c, *t_hi, *t_c, *ve_hi, *ve_c, *p_hi, *p_c;
    fp16 *wqT_hi, *wqT_c, *wkT_hi, *wkT_c, *wvT_hi, *wvT_c;
    fp16 *wp_hi, *wp_c, *m2_hi, *m2_c, *wpv_hi, *wpv_c;
    float *s, *u, *vbp;
    cudaGetSymbolAddress((void**)&ht_hi, g_ht_hi);
    cudaGetSymbolAddress((void**)&ht_c, g_ht_c);
    cudaGetSymbolAddress((void**)&t_hi, g_t_hi);
    cudaGetSymbolAddress((void**)&t_c, g_t_c);
    cudaGetSymbolAddress((void**)&ve_hi, g_ve_hi);
    cudaGetSymbolAddress((void**)&ve_c, g_ve_c);
    cudaGetSymbolAddress((void**)&p_hi, g_p_hi);
    cudaGetSymbolAddress((void**)&p_c, g_p_c);
    cudaGetSymbolAddress((void**)&wqT_hi, g_wqT_hi);
    cudaGetSymbolAddress((void**)&wqT_c, g_wqT_c);
    cudaGetSymbolAddress((void**)&wkT_hi, g_wkT_hi);
    cudaGetSymbolAddress((void**)&wkT_c, g_wkT_c);
    cudaGetSymbolAddress((void**)&wvT_hi, g_wvT_hi);
    cudaGetSymbolAddress((void**)&wvT_c, g_wvT_c);
    cudaGetSymbolAddress((void**)&wp_hi, g_wp_hi);
    cudaGetSymbolAddress((void**)&wp_c, g_wp_c);
    cudaGetSymbolAddress((void**)&m2_hi, g_m2_hi);
    cudaGetSymbolAddress((void**)&m2_c, g_m2_c);
    cudaGetSymbolAddress((void**)&wpv_hi, g_wpv_hi);
    cudaGetSymbolAddress((void**)&wpv_c, g_wpv_c);
    cudaGetSymbolAddress((void**)&s, g_s);
    cudaGetSymbolAddress((void**)&u, g_u);
    cudaGetSymbolAddress((void**)&vbp, g_vbp);

    cudaFuncSetAttribute(gemm_mma<0>, cudaFuncAttributeMaxDynamicSharedMemorySize, SMEM_T3);
    cudaFuncSetAttribute(gemm_mma<1>, cudaFuncAttributeMaxDynamicSharedMemorySize, SMEM_T3);
    cudaFuncSetAttribute(gemm_mma<2>, cudaFuncAttributeMaxDynamicSharedMemorySize, SMEM_T3);
    cudaFuncSetAttribute(gemm_mma<3>, cudaFuncAttributeMaxDynamicSharedMemorySize, SMEM_T3);
    cudaFuncSetAttribute(gemm_mma<4>, cudaFuncAttributeMaxDynamicSharedMemorySize, SMEM_T3);

    const size_t sHC = (size_t)HW * CC;
    const size_t sSS = (size_t)HW * HW;
    const float scale = 0.044194173824159216f;  // 512^-0.5

    // ---- fork ------------------------------------------------------------
    cudaEventRecord(g_aux.e_fork, 0);
    cudaStreamWaitEvent(g_aux.sw, g_aux.e_fork, 0);
    for (int i = 0; i < NCHUNK - 1; i++)
        cudaStreamWaitEvent(g_aux.sc[i], g_aux.e_fork, 0);

    // weight-prep stream
    cudaStream_t sw = g_aux.sw;
    wtransT<<<dim3(16, 16, 3), dim3(32, 8), 0, sw>>>(q_w, k_w, v_w);
    wsplit<<<CC * CC / 256, 256, 0, sw>>>(p_w);
    ubias<<<CC / 128, 128, 0, sw>>>(q_b, k_w);
    vbias<<<CC, 256, 0, sw>>>(p_w, v_b);
    gemm_mma<3><<<dim3(4, 4, 1), 256, SMEM_T3, sw>>>(
        wkT_hi, wkT_c, 0, wqT_hi, wqT_c, 0, CC,
        nullptr, 0.f, nullptr, m2_hi, m2_c, nullptr, CC, 0);
    gemm_mma<3><<<dim3(4, 4, 1), 256, SMEM_T3, sw>>>(
        wp_hi, wp_c, 0, wvT_hi, wvT_c, 0, CC,
        nullptr, 0.f, nullptr, wpv_hi, wpv_c, nullptr, CC, 0);
    cudaEventRecord(g_aux.e_wp, sw);

    // per-chunk chains
    for (int c = 0; c < NCHUNK; c++) {
        cudaStream_t st = (c == 0) ? (cudaStream_t)0 : g_aux.sc[c - 1];
        const int b0 = c * CB;
        const size_t oHC = (size_t)b0 * sHC;
        const size_t oSS = (size_t)b0 * sSS;
        const size_t oX = (size_t)b0 * CC * HW;

        gn_stats<<<CB * G, 256, 0, st>>>(x, b0);
        gn_transpose<<<dim3(HW / 32, CC / 32, CB), dim3(32, 8), 0, st>>>(
            x, gn_w, gn_b, b0);

        cudaStreamWaitEvent(st, g_aux.e_wp, 0);

        // Ve[d][j] = Wpv[d]·Ht[j] + (Wp·vb)[d]
        gemm_mma<1><<<dim3(8, 4, CB), 256, SMEM_T3, st>>>(
            wpv_hi, wpv_c, 0, ht_hi + oHC, ht_c + oHC, sHC, CC,
            vbp, 0.f, nullptr, ve_hi + oHC, ve_c + oHC, nullptr, HW, sHC);
        // T[i][b] = Ht[i]·M2[b] + u[b]
        gemm_mma<0><<<dim3(4, 8, CB), 256, SMEM_T3, st>>>(
            ht_hi + oHC, ht_c + oHC, sHC, m2_hi, m2_c, 0, CC,
            u, 0.f, nullptr, t_hi + oHC, t_c + oHC, nullptr, CC, sHC);
        // S[i][j] = scale * T[i]·Ht[j]
        gemm_mma<2><<<dim3(8, 8, CB), 256, SMEM_T3, st>>>(
            t_hi + oHC, t_c + oHC, sHC, ht_hi + oHC, ht_c + oHC, sHC, CC,
            nullptr, scale, nullptr, nullptr, nullptr, s + oSS, HW, sSS);
        softmax_kernel<<<CB * HW, 256, 0, st>>>(s + oSS, p_hi + oSS, p_c + oSS);
        // out[d][i] = x[d][i] + Ve[d]·P[i] + p_b[d]
        gemm_mma<4><<<dim3(8, 4, CB), 256, SMEM_T3, st>>>(
            ve_hi + oHC, ve_c + oHC, sHC, p_hi + oSS, p_c + oSS, sSS, HW,
            p_b, 0.f, x + oX, nullptr, nullptr, out + oX, HW, sHC);

        if (c > 0) cudaEventRecord(g_aux.e_done[c - 1], st);
    }

    // final join on main stream
    for (int i = 0; i < NCHUNK - 1; i++)
        cudaStreamWaitEvent(0, g_aux.e_done[i], 0);
}

// round 17
// speedup vs baseline: 1.0358x; 1.0358x over previous
#include <cuda_runtime.h>
#include <cuda_fp16.h>
#include <cstdint>

#define BATCH 16
#define CC 512
#define HW 1024
#define G 32
#define CG 16
#define EPS 1e-5f

#define NCHUNK 4
#define CB (BATCH / NCHUNK)

typedef __half fp16;

// combo encoding: x ~ h + l; c = fl16(h + 64*l).
// 2-MMA GEMM: acc1 += Ah*Bh (f32), acc2 += Ac*Bc (f16),
// D = acc1 + (acc2-acc1)/64 = AhBh + AhBl + AlBh + 64*AlBl + O(2^-17)
#define LAM 64.f
#define LAMINV 0.015625f

// ---------------------------------------------------------------------------
// Scratch (device globals)
// ---------------------------------------------------------------------------
__device__ float g_stats[BATCH * G * 2];
__device__ __align__(16) fp16 g_ht_hi[BATCH * HW * CC], g_ht_lo[BATCH * HW * CC];
__device__ __align__(16) fp16 g_ht_c[BATCH * HW * CC];
__device__ __align__(16) fp16 g_t_hi[BATCH * HW * CC],  g_t_lo[BATCH * HW * CC];
__device__ __align__(16) fp16 g_ve_hi[BATCH * CC * HW], g_ve_c[BATCH * CC * HW];
__device__ __align__(16) float g_s[(size_t)BATCH * HW * HW];
__device__ __align__(16) fp16 g_p_hi[(size_t)BATCH * HW * HW];
__device__ __align__(16) fp16 g_p_c[(size_t)BATCH * HW * HW];
__device__ __align__(16) fp16 g_wqT_hi[CC * CC], g_wqT_lo[CC * CC];
__device__ __align__(16) fp16 g_wkT_hi[CC * CC], g_wkT_lo[CC * CC];
__device__ __align__(16) fp16 g_wvT_hi[CC * CC], g_wvT_lo[CC * CC];
__device__ __align__(16) fp16 g_wp_hi[CC * CC],  g_wp_lo[CC * CC];
__device__ __align__(16) fp16 g_m2_hi[CC * CC],  g_m2_lo[CC * CC];
__device__ __align__(16) fp16 g_wpv_hi[CC * CC], g_wpv_lo[CC * CC];
__device__ __align__(16) fp16 g_wpv_c[CC * CC];
__device__ float g_u[CC], g_vbp[CC];

// ---------------------------------------------------------------------------
// Streams + events (created once at load)
// ---------------------------------------------------------------------------
namespace {
struct AuxStreams {
    cudaStream_t sc[NCHUNK - 1] = {};
    cudaStream_t sw = nullptr;
    cudaEvent_t e_fork = nullptr, e_wp = nullptr;
    cudaEvent_t e_done[NCHUNK - 1] = {};
    AuxStreams() {
        for (int i = 0; i < NCHUNK - 1; i++) {
            cudaStreamCreateWithFlags(&sc[i], cudaStreamNonBlocking);
            cudaEventCreateWithFlags(&e_done[i], cudaEventDisableTiming);
        }
        cudaStreamCreateWithFlags(&sw, cudaStreamNonBlocking);
        cudaEventCreateWithFlags(&e_fork, cudaEventDisableTiming);
        cudaEventCreateWithFlags(&e_wp, cudaEventDisableTiming);
    }
};
AuxStreams g_aux;
}  // namespace

// ---------------------------------------------------------------------------
// PTX helpers
// ---------------------------------------------------------------------------
__device__ __forceinline__ uint32_t smem_u32(const void* p) {
    uint32_t a;
    asm("{ .reg .u64 t; cvta.to.shared.u64 t, %1; cvt.u32.u64 %0, t; }"
        : "=r"(a) : "l"(p));
    return a;
}
__device__ __forceinline__ void cpa16(uint32_t dst, const void* src) {
    asm volatile("cp.async.ca.shared.global [%0], [%1], 16;"
                 :: "r"(dst), "l"(src));
}
#define CP_COMMIT() asm volatile("cp.async.commit_group;" ::: "memory")
#define CP_WAIT1() asm volatile("cp.async.wait_group 1;" ::: "memory")

__device__ __forceinline__ void ldsm_x4(uint32_t* r, uint32_t addr) {
    asm volatile(
        "ldmatrix.sync.aligned.m8n8.x4.shared.b16 {%0,%1,%2,%3}, [%4];"
        : "=r"(r[0]), "=r"(r[1]), "=r"(r[2]), "=r"(r[3]) : "r"(addr));
}
__device__ __forceinline__ void mma16816(float* c, const uint32_t* a,
                                         const uint32_t* b) {
    asm volatile(
        "mma.sync.aligned.m16n8k16.row.col.f32.f16.f16.f32 "
        "{%0,%1,%2,%3}, {%4,%5,%6,%7}, {%8,%9}, {%0,%1,%2,%3};"
        : "+f"(c[0]), "+f"(c[1]), "+f"(c[2]), "+f"(c[3])
        : "r"(a[0]), "r"(a[1]), "r"(a[2]), "r"(a[3]), "r"(b[0]), "r"(b[1]));
}
// f16-accumulator MMA (acc2; positions {lo0,lo1},{lo2,lo3} match f32 c0..c3)
__device__ __forceinline__ void mma16816h(uint32_t* c, const uint32_t* a,
                                          const uint32_t* b) {
    asm volatile(
        "mma.sync.aligned.m16n8k16.row.col.f16.f16.f16.f16 "
        "{%0,%1}, {%2,%3,%4,%5}, {%6,%7}, {%0,%1};"
        : "+r"(c[0]), "+r"(c[1])
        : "r"(a[0]), "r"(a[1]), "r"(a[2]), "r"(a[3]), "r"(b[0]), "r"(b[1]));
}

__device__ __forceinline__ void split_hc(float v, fp16& h, fp16& c) {
    h = __float2half(v);
    float hf = __half2float(h);
    fp16 l = __float2half(v - hf);
    c = __float2half(hf + LAM * __half2float(l));
}

// Swizzled 64B-row layout: conflict-free for ldmatrix + cp.async
#define SWZ(row, kb) \
    ((uint32_t)(row) * 64u + (((((uint32_t)(kb)) >> 4) ^ (((uint32_t)(row) >> 1) & 3u)) << 4))

#define MATB 8192u
#define NSTAGE 3
#define SMEM_T3 (NSTAGE * 4 * MATB)   // 98304: 4 matrices

// ---------------------------------------------------------------------------
// 3-term split-fp16 GEMM (pre-softmax; proven fp32-grade):
// D ~= Ah*Bh + Ah*Bl + Al*Bh, 128x128 tile, 4 warps (64x64), BK=32.
// MODE 0: +bias[n] ; MODE 2: *scale f32 out ; MODE 3: plain
// Optional Occ: also store combo c = fl16(h + 64*l).
// ---------------------------------------------------------------------------
template <int MODE>
__global__ void __launch_bounds__(128, 2)
gemm_mma(const fp16* __restrict__ Ahi, const fp16* __restrict__ Alo, size_t sA,
         const fp16* __restrict__ Bhi, const fp16* __restrict__ Blo, size_t sB,
         int K, const float* __restrict__ bias, float scale,
         fp16* __restrict__ Ohi, fp16* __restrict__ Olo, fp16* __restrict__ Occ,
         float* __restrict__ Of, int ldO, size_t sO) {
    extern __shared__ char smem[];
    const uint32_t sb = smem_u32(smem);
    constexpr uint32_t STB = 4 * MATB;

    const int t = threadIdx.x;
    const int w = t >> 5, lane = t & 31;
    const int g = lane >> 2, tg = lane & 3;
    const int wm = (w >> 1) * 64, wn = (w & 1) * 64;
    const int bz = blockIdx.z;
    const int n0 = blockIdx.x * 128, m0 = blockIdx.y * 128;

    const fp16* arh = Ahi + bz * sA + (size_t)m0 * K;
    const fp16* arl = Alo + bz * sA + (size_t)m0 * K;
    const fp16* brh = Bhi + bz * sB + (size_t)n0 * K;
    const fp16* brl = Blo + bz * sB + (size_t)n0 * K;

    float acc[4][8][4];
#pragma unroll
    for (int i = 0; i < 4; i++)
#pragma unroll
        for (int j = 0; j < 8; j++)
#pragma unroll
            for (int e = 0; e < 4; e++) acc[i][j][e] = 0.f;

    const int rbase = t >> 2, seg = t & 3;

    const uint32_t a_row = (uint32_t)(wm + ((lane >> 3) & 1) * 8 + (lane & 7));
    const uint32_t a_kb = ((lane >> 4) & 1) * 16;
    const uint32_t b_row = (uint32_t)(wn + ((lane >> 4) & 1) * 8 + (lane & 7));
    const uint32_t b_kb = ((lane >> 3) & 1) * 16;

    const int nsteps = K >> 5;

    auto issue = [&](int s) {
        int kc = s << 5;
        uint32_t b0 = sb + (uint32_t)(s % NSTAGE) * STB;
#pragma unroll
        for (int j = 0; j < 4; j++) {
            int r = rbase + 32 * j;
            uint32_t so = SWZ(r, seg * 16);
            size_t go = (size_t)r * K + kc + seg * 8;
            cpa16(b0 + so, arh + go);
            cpa16(b0 + MATB + so, arl + go);
            cpa16(b0 + 2 * MATB + so, brh + go);
            cpa16(b0 + 3 * MATB + so, brl + go);
        }
        CP_COMMIT();
    };

    issue(0);
    issue(1);

    for (int s = 0; s < nsteps; s++) {
        CP_WAIT1();
        __syncthreads();
        if (s + 2 < nsteps) issue(s + 2);

        uint32_t stg = sb + (uint32_t)(s % NSTAGE) * STB;
        uint32_t pAh = stg, pAl = stg + MATB;
        uint32_t pBh = stg + 2 * MATB, pBl = stg + 3 * MATB;
#pragma unroll
        for (int kk = 0; kk < 2; kk++) {
            uint32_t kb = (uint32_t)kk * 32;
            uint32_t Ah[4][4], Al[4][4];
#pragma unroll
            for (int mf = 0; mf < 4; mf++) {
                uint32_t ad = SWZ(a_row + mf * 16, kb + a_kb);
                ldsm_x4(Ah[mf], pAh + ad);
                ldsm_x4(Al[mf], pAl + ad);
            }
#pragma unroll
            for (int p = 0; p < 4; p++) {
                uint32_t bd = SWZ(b_row + p * 16, kb + b_kb);
                uint32_t Bh[4], Bl[4];
                ldsm_x4(Bh, pBh + bd);
                ldsm_x4(Bl, pBl + bd);
#pragma unroll
                for (int mf = 0; mf < 4; mf++) {
                    mma16816(acc[mf][2 * p], Ah[mf], Bh);
                    mma16816(acc[mf][2 * p], Ah[mf], Bl);
                    mma16816(acc[mf][2 * p], Al[mf], Bh);
                    mma16816(acc[mf][2 * p + 1], Ah[mf], Bh + 2);
                    mma16816(acc[mf][2 * p + 1], Ah[mf], Bl + 2);
                    mma16816(acc[mf][2 * p + 1], Al[mf], Bh + 2);
                }
            }
        }
        __syncthreads();
    }

#pragma unroll
    for (int mf = 0; mf < 4; mf++) {
        int mA = m0 + wm + mf * 16 + g;
        int mB = mA + 8;
#pragma unroll
        for (int nf = 0; nf < 8; nf++) {
            int n = n0 + wn + nf * 8 + tg * 2;
            float v0 = acc[mf][nf][0], v1 = acc[mf][nf][1];
            float v2 = acc[mf][nf][2], v3 = acc[mf][nf][3];
            if (MODE == 0) {
                float bn0 = bias[n], bn1 = bias[n + 1];
                v0 += bn0; v1 += bn1; v2 += bn0; v3 += bn1;
            }
            if (MODE == 2) { v0 *= scale; v1 *= scale; v2 *= scale; v3 *= scale; }
            size_t iA = bz * sO + (size_t)mA * ldO + n;
            size_t iB = bz * sO + (size_t)mB * ldO + n;
            if (MODE == 2) {
                *(float2*)&Of[iA] = make_float2(v0, v1);
                *(float2*)&Of[iB] = make_float2(v2, v3);
            } else {
                fp16 h0 = __float2half(v0), h1 = __float2half(v1);
                fp16 h2 = __float2half(v2), h3 = __float2half(v3);
                __half2 hA; hA.x = h0; hA.y = h1;
                __half2 hB; hB.x = h2; hB.y = h3;
                *(__half2*)&Ohi[iA] = hA;
                *(__half2*)&Ohi[iB] = hB;
                float l0 = v0 - __half2float(h0), l1 = v1 - __half2float(h1);
                float l2 = v2 - __half2float(h2), l3 = v3 - __half2float(h3);
                __half2 lA, lB;
                lA.x = __float2half(l0); lA.y = __float2half(l1);
                lB.x = __float2half(l2); lB.y = __float2half(l3);
                *(__half2*)&Olo[iA] = lA;
                *(__half2*)&Olo[iB] = lB;
                if (Occ) {
                    __half2 cA, cB;
                    cA.x = __float2half(__half2float(h0) + LAM * __half2float(lA.x));
                    cA.y = __float2half(__half2float(h1) + LAM * __half2float(lA.y));
                    cB.x = __float2half(__half2float(h2) + LAM * __half2float(lB.x));
                    cB.y = __float2half(__half2float(h3) + LAM * __half2float(lB.y));
                    *(__half2*)&Occ[iA] = cA;
                    *(__half2*)&Occ[iB] = cB;
                }
            }
        }
    }
}

// ---------------------------------------------------------------------------
// 2-MMA compensated GEMM (post-softmax): acc1=Ah*Bh (f32), acc2=Ac*Bc (f16),
// D = acc1 + (acc2-acc1)/64. 128x128 tile, 4 warps (64x64), BK=32.
// MODE 1: +bias[m], h/c out ; MODE 4: +bias[m]+resid, f32 out
// ---------------------------------------------------------------------------
template <int MODE>
__global__ void __launch_bounds__(128, 2)
gemm2(const fp16* __restrict__ Ahi, const fp16* __restrict__ Acb, size_t sA,
      const fp16* __restrict__ Bhi, const fp16* __restrict__ Bcb, size_t sB,
      int K, const float* __restrict__ bias,
      const float* __restrict__ resid,
      fp16* __restrict__ Ohi, fp16* __restrict__ Ocb, float* __restrict__ Of,
      int ldO, size_t sO) {
    extern __shared__ char smem[];
    const uint32_t sb = smem_u32(smem);
    constexpr uint32_t STB = 4 * MATB;

    const int t = threadIdx.x;
    const int w = t >> 5, lane = t & 31;
    const int g = lane >> 2, tg = lane & 3;
    const int wm = (w >> 1) * 64, wn = (w & 1) * 64;
    const int bz = blockIdx.z;
    const int n0 = blockIdx.x * 128, m0 = blockIdx.y * 128;

    const fp16* arh = Ahi + bz * sA + (size_t)m0 * K;
    const fp16* arc = Acb + bz * sA + (size_t)m0 * K;
    const fp16* brh = Bhi + bz * sB + (size_t)n0 * K;
    const fp16* brc = Bcb + bz * sB + (size_t)n0 * K;

    float acc1[4][8][4];
    uint32_t acc2[4][8][2];
#pragma unroll
    for (int i = 0; i < 4; i++)
#pragma unroll
        for (int j = 0; j < 8; j++) {
#pragma unroll
            for (int e = 0; e < 4; e++) acc1[i][j][e] = 0.f;
            acc2[i][j][0] = 0u;
            acc2[i][j][1] = 0u;
        }

    const int rbase = t >> 2, seg = t & 3;

    const uint32_t a_row = (uint32_t)(wm + ((lane >> 3) & 1) * 8 + (lane & 7));
    const uint32_t a_kb = ((lane >> 4) & 1) * 16;
    const uint32_t b_row = (uint32_t)(wn + ((lane >> 4) & 1) * 8 + (lane & 7));
    const uint32_t b_kb = ((lane >> 3) & 1) * 16;

    const int nsteps = K >> 5;

    auto issue = [&](int s) {
        int kc = s << 5;
        uint32_t b0 = sb + (uint32_t)(s % NSTAGE) * STB;
#pragma unroll
        for (int j = 0; j < 4; j++) {
            int r = rbase + 32 * j;
            uint32_t so = SWZ(r, seg * 16);
            size_t go = (size_t)r * K + kc + seg * 8;
            cpa16(b0 + so, arh + go);
            cpa16(b0 + MATB + so, arc + go);
            cpa16(b0 + 2 * MATB + so, brh + go);
            cpa16(b0 + 3 * MATB + so, brc + go);
        }
        CP_COMMIT();
    };

    issue(0);
    issue(1);

    for (int s = 0; s < nsteps; s++) {
        CP_WAIT1();
        __syncthreads();
        if (s + 2 < nsteps) issue(s + 2);

        uint32_t stg = sb + (uint32_t)(s % NSTAGE) * STB;
        uint32_t pAh = stg, pAc = stg + MATB;
        uint32_t pBh = stg + 2 * MATB, pBc = stg + 3 * MATB;
#pragma unroll
        for (int kk = 0; kk < 2; kk++) {
            uint32_t kb = (uint32_t)kk * 32;
            uint32_t Ah[4][4], Ac[4][4];
#pragma unroll
            for (int mf = 0; mf < 4; mf++) {
                uint32_t ad = SWZ(a_row + mf * 16, kb + a_kb);
                ldsm_x4(Ah[mf], pAh + ad);
                ldsm_x4(Ac[mf], pAc + ad);
            }
#pragma unroll
            for (int p = 0; p < 4; p++) {
                uint32_t bd = SWZ(b_row + p * 16, kb + b_kb);
                uint32_t Bh[4], Bc[4];
                ldsm_x4(Bh, pBh + bd);
                ldsm_x4(Bc, pBc + bd);
#pragma unroll
                for (int mf = 0; mf < 4; mf++) {
                    mma16816(acc1[mf][2 * p], Ah[mf], Bh);
                    mma16816(acc1[mf][2 * p + 1], Ah[mf], Bh + 2);
                    mma16816h(acc2[mf][2 * p], Ac[mf], Bc);
                    mma16816h(acc2[mf][2 * p + 1], Ac[mf], Bc + 2);
                }
            }
        }
        __syncthreads();
    }

#pragma unroll
    for (int mf = 0; mf < 4; mf++) {
        int mA = m0 + wm + mf * 16 + g;
        int mB = mA + 8;
        float bmA = bias[mA], bmB = bias[mB];
#pragma unroll
        for (int nf = 0; nf < 8; nf++) {
            int n = n0 + wn + nf * 8 + tg * 2;
            float2 a2l = __half22float2(*(__half2*)&acc2[mf][nf][0]);
            float2 a2h = __half22float2(*(__half2*)&acc2[mf][nf][1]);
            float v0 = acc1[mf][nf][0] + LAMINV * (a2l.x - acc1[mf][nf][0]);
            float v1 = acc1[mf][nf][1] + LAMINV * (a2l.y - acc1[mf][nf][1]);
            float v2 = acc1[mf][nf][2] + LAMINV * (a2h.x - acc1[mf][nf][2]);
            float v3 = acc1[mf][nf][3] + LAMINV * (a2h.y - acc1[mf][nf][3]);
            v0 += bmA; v1 += bmA; v2 += bmB; v3 += bmB;
            size_t iA = bz * sO + (size_t)mA * ldO + n;
            size_t iB = bz * sO + (size_t)mB * ldO + n;
            if (MODE == 4) {
                v0 += resid[iA]; v1 += resid[iA + 1];
                v2 += resid[iB]; v3 += resid[iB + 1];
                *(float2*)&Of[iA] = make_float2(v0, v1);
                *(float2*)&Of[iB] = make_float2(v2, v3);
            } else {
                fp16 h0, c0, h1, c1, h2, c2, h3, c3;
                split_hc(v0, h0, c0); split_hc(v1, h1, c1);
                split_hc(v2, h2, c2); split_hc(v3, h3, c3);
                __half2 hA; hA.x = h0; hA.y = h1;
                __half2 hB; hB.x = h2; hB.y = h3;
                __half2 cA; cA.x = c0; cA.y = c1;
                __half2 cB; cB.x = c2; cB.y = c3;
                *(__half2*)&Ohi[iA] = hA;
                *(__half2*)&Ohi[iB] = hB;
                *(__half2*)&Ocb[iA] = cA;
                *(__half2*)&Ocb[iB] = cB;
            }
        }
    }
}

// ---------------------------------------------------------------------------
// GroupNorm stats (per-chunk)
// ---------------------------------------------------------------------------
__global__ void gn_stats(const float* __restrict__ x, int b0) {
    int bg = blockIdx.x + b0 * G;
    int bb = bg / G, g = bg % G;
    const float* xp = x + ((size_t)bb * CC + (size_t)g * CG) * HW;
    const int n = CG * HW;

    float s = 0.f, ss = 0.f;
    for (int i = threadIdx.x; i < n; i += blockDim.x) {
        float v = xp[i];
        s += v;
        ss += v * v;
    }
    __shared__ float sh0[256], sh1[256];
    sh0[threadIdx.x] = s;
    sh1[threadIdx.x] = ss;
    __syncthreads();
    for (int o = 128; o > 0; o >>= 1) {
        if (threadIdx.x < o) {
            sh0[threadIdx.x] += sh0[threadIdx.x + o];
            sh1[threadIdx.x] += sh1[threadIdx.x + o];
        }
        __syncthreads();
    }
    if (threadIdx.x == 0) {
        float mu = sh0[0] / n;
        float var = sh1[0] / n - mu * mu;
        g_stats[bg * 2] = mu;
        g_stats[bg * 2 + 1] = rsqrtf(var + EPS);
    }
}

// GroupNorm apply + transpose: writes Ht hi, lo, combo (per-chunk)
__global__ void gn_transpose(const float* __restrict__ x,
                             const float* __restrict__ gw,
                             const float* __restrict__ gb, int b0) {
    __shared__ float tile[32][33];
    int bz = blockIdx.z + b0;
    int i0 = blockIdx.x * 32, c0 = blockIdx.y * 32;
    int tx = threadIdx.x, ty = threadIdx.y;
    const float* xb = x + (size_t)bz * CC * HW;
#pragma unroll
    for (int r = 0; r < 4; r++) {
        int c = c0 + ty + r * 8;
        float mu = g_stats[(bz * G + (c >> 4)) * 2];
        float ri = g_stats[(bz * G + (c >> 4)) * 2 + 1];
        float v = xb[(size_t)c * HW + i0 + tx];
        tile[ty + r * 8][tx] = (v - mu) * ri * gw[c] + gb[c];
    }
    __syncthreads();
    size_t ob = (size_t)bz * HW * CC;
#pragma unroll
    for (int r = 0; r < 4; r++) {
        int i = i0 + ty + r * 8;
        float v = tile[tx][ty + r * 8];
        fp16 h = __float2half(v);
        float hf = __half2float(h);
        fp16 l = __float2half(v - hf);
        fp16 c = __float2half(hf + LAM * __half2float(l));
        size_t idx = ob + (size_t)i * CC + c0 + tx;
        g_ht_hi[idx] = h;
        g_ht_lo[idx] = l;
        g_ht_c[idx] = c;
    }
}

// Transpose+split 3 weight matrices (h, l)
__global__ void wtransT(const float* __restrict__ w0, const float* __restrict__ w1,
                        const float* __restrict__ w2) {
    __shared__ float tile[32][33];
    int z = blockIdx.z;
    const float* w = z == 0 ? w0 : z == 1 ? w1 : w2;
    fp16* ohi = z == 0 ? g_wqT_hi : z == 1 ? g_wkT_hi : g_wvT_hi;
    fp16* olo = z == 0 ? g_wqT_lo : z == 1 ? g_wkT_lo : g_wvT_lo;
    int d0 = blockIdx.x * 32, a0 = blockIdx.y * 32;
    int tx = threadIdx.x, ty = threadIdx.y;
#pragma unroll
    for (int r = 0; r < 4; r++)
        tile[ty + r * 8][tx] = w[(size_t)(d0 + ty + r * 8) * CC + a0 + tx];
    __syncthreads();
#pragma unroll
    for (int r = 0; r < 4; r++) {
        int a = a0 + ty + r * 8;
        float v = tile[tx][ty + r * 8];
        fp16 h = __float2half(v);
        size_t idx = (size_t)a * CC + d0 + tx;
        ohi[idx] = h;
        olo[idx] = __float2half(v - __half2float(h));
    }
}

// Straight split of Wp (h, l)
__global__ void wsplit(const float* __restrict__ w) {
    int i = blockIdx.x * blockDim.x + threadIdx.x;
    float v = w[i];
    fp16 h = __float2half(v);
    g_wp_hi[i] = h;
    g_wp_lo[i] = __float2half(v - __half2float(h));
}

// u[b] = sum_d qb[d]*Wk[d][b]
__global__ void ubias(const float* __restrict__ qb, const float* __restrict__ wk) {
    int b = blockIdx.x * blockDim.x + threadIdx.x;
    float s = 0.f;
    for (int d = 0; d < CC; d++) s += qb[d] * wk[(size_t)d * CC + b];
    g_u[b] = s;
}

// vbp[d] = sum_c Wp[d][c]*vb[c]
__global__ void vbias(const float* __restrict__ wp, const float* __restrict__ vb) {
    int d = blockIdx.x;
    float s = 0.f;
    for (int c = threadIdx.x; c < CC; c += blockDim.x)
        s += wp[(size_t)d * CC + c] * vb[c];
    __shared__ float sh[256];
    sh[threadIdx.x] = s;
    __syncthreads();
    for (int o = 128; o > 0; o >>= 1) {
        if (threadIdx.x < o) sh[threadIdx.x] += sh[threadIdx.x + o];
        __syncthreads();
    }
    if (threadIdx.x == 0) g_vbp[d] = sh[0];
}

// Row softmax over 1024 columns; writes P as fp16 h/c (consumed by gemm2)
__global__ void softmax_kernel(const float* __restrict__ S,
                               fp16* __restrict__ Ph, fp16* __restrict__ Pc) {
    const float* row = S + (size_t)blockIdx.x * HW;
    int t = threadIdx.x;
    float4 v = ((const float4*)row)[t];

    __shared__ float sh[256];
    float m = fmaxf(fmaxf(v.x, v.y), fmaxf(v.z, v.w));
    sh[t] = m;
    __syncthreads();
    for (int o = 128; o > 0; o >>= 1) {
        if (t < o) sh[t] = fmaxf(sh[t], sh[t + o]);
        __syncthreads();
    }
    m = sh[0];
    __syncthreads();

    v.x = __expf(v.x - m); v.y = __expf(v.y - m);
    v.z = __expf(v.z - m); v.w = __expf(v.w - m);
    sh[t] = v.x + v.y + v.z + v.w;
    __syncthreads();
    for (int o = 128; o > 0; o >>= 1) {
        if (t < o) sh[t] += sh[t + o];
        __syncthreads();
    }
    float inv = 1.0f / sh[0];
    float p[4] = {v.x * inv, v.y * inv, v.z * inv, v.w * inv};
    size_t base = (size_t)blockIdx.x * HW + t * 4;
#pragma unroll
    for (int e = 0; e < 4; e++) {
        fp16 h, c;
        split_hc(p[e], h, c);
        Ph[base + e] = h;
        Pc[base + e] = c;
    }
}

// ---------------------------------------------------------------------------
extern "C" void kernel_launch(void* const* d_in, const int* in_sizes, int n_in,
                              void* d_out, int out_size) {
    const float* x    = (const float*)d_in[0];
    const float* gn_w = (const float*)d_in[2];
    const float* gn_b = (const float*)d_in[3];
    const float* q_w  = (const float*)d_in[4];
    const float* q_b  = (const float*)d_in[5];
    const float* k_w  = (const float*)d_in[6];
    const float* v_w  = (const float*)d_in[8];
    const float* v_b  = (const float*)d_in[9];
    const float* p_w  = (const float*)d_in[10];
    const float* p_b  = (const float*)d_in[11];
    float* out = (float*)d_out;

    fp16 *ht_hi, *ht_lo, *ht_c, *t_hi, *t_lo, *ve_hi, *ve_c, *p_hi, *p_c;
    fp16 *wqT_hi, *wqT_lo, *wkT_hi, *wkT_lo, *wvT_hi, *wvT_lo;
    fp16 *wp_hi, *wp_lo, *m2_hi, *m2_lo, *wpv_hi, *wpv_lo, *wpv_c;
    float *s, *u, *vbp;
    cudaGetSymbolAddress((void**)&ht_hi, g_ht_hi);
    cudaGetSymbolAddress((void**)&ht_lo, g_ht_lo);
    cudaGetSymbolAddress((void**)&ht_c, g_ht_c);
    cudaGetSymbolAddress((void**)&t_hi, g_t_hi);
    cudaGetSymbolAddress((void**)&t_lo, g_t_lo);
    cudaGetSymbolAddress((void**)&ve_hi, g_ve_hi);
    cudaGetSymbolAddress((void**)&ve_c, g_ve_c);
    cudaGetSymbolAddress((void**)&p_hi, g_p_hi);
    cudaGetSymbolAddress((void**)&p_c, g_p_c);
    cudaGetSymbolAddress((void**)&wqT_hi, g_wqT_hi);
    cudaGetSymbolAddress((void**)&wqT_lo, g_wqT_lo);
    cudaGetSymbolAddress((void**)&wkT_hi, g_wkT_hi);
    cudaGetSymbolAddress((void**)&wkT_lo, g_wkT_lo);
    cudaGetSymbolAddress((void**)&wvT_hi, g_wvT_hi);
    cudaGetSymbolAddress((void**)&wvT_lo, g_wvT_lo);
    cudaGetSymbolAddress((void**)&wp_hi, g_wp_hi);
    cudaGetSymbolAddress((void**)&wp_lo, g_wp_lo);
    cudaGetSymbolAddress((void**)&m2_hi, g_m2_hi);
    cudaGetSymbolAddress((void**)&m2_lo, g_m2_lo);
    cudaGetSymbolAddress((void**)&wpv_hi, g_wpv_hi);
    cudaGetSymbolAddress((void**)&wpv_lo, g_wpv_lo);
    cudaGetSymbolAddress((void**)&wpv_c, g_wpv_c);
    cudaGetSymbolAddress((void**)&s, g_s);
    cudaGetSymbolAddress((void**)&u, g_u);
    cudaGetSymbolAddress((void**)&vbp, g_vbp);

    cudaFuncSetAttribute(gemm_mma<0>, cudaFuncAttributeMaxDynamicSharedMemorySize, SMEM_T3);
    cudaFuncSetAttribute(gemm_mma<2>, cudaFuncAttributeMaxDynamicSharedMemorySize, SMEM_T3);
    cudaFuncSetAttribute(gemm_mma<3>, cudaFuncAttributeMaxDynamicSharedMemorySize, SMEM_T3);
    cudaFuncSetAttribute(gemm2<1>, cudaFuncAttributeMaxDynamicSharedMemorySize, SMEM_T3);
    cudaFuncSetAttribute(gemm2<4>, cudaFuncAttributeMaxDynamicSharedMemorySize, SMEM_T3);

    const size_t sHC = (size_t)HW * CC;
    const size_t sSS = (size_t)HW * HW;
    const float scale = 0.044194173824159216f;  // 512^-0.5

    // ---- fork ------------------------------------------------------------
    cudaEventRecord(g_aux.e_fork, 0);
    cudaStreamWaitEvent(g_aux.sw, g_aux.e_fork, 0);
    for (int i = 0; i < NCHUNK - 1; i++)
        cudaStreamWaitEvent(g_aux.sc[i], g_aux.e_fork, 0);

    // weight-prep stream
    cudaStream_t sw = g_aux.sw;
    wtransT<<<dim3(16, 16, 3), dim3(32, 8), 0, sw>>>(q_w, k_w, v_w);
    wsplit<<<CC * CC / 256, 256, 0, sw>>>(p_w);
    ubias<<<CC / 128, 128, 0, sw>>>(q_b, k_w);
    vbias<<<CC, 256, 0, sw>>>(p_w, v_b);
    // M2[b][a] = sum_d Wk[d][b]*Wq[d][a]  (h,l out)
    gemm_mma<3><<<dim3(4, 4, 1), 128, SMEM_T3, sw>>>(
        wkT_hi, wkT_lo, 0, wqT_hi, wqT_lo, 0, CC,
        nullptr, 0.f, m2_hi, m2_lo, nullptr, nullptr, CC, 0);
    // Wpv[d][c'] = sum_c Wp[d][c]*Wv[c][c']  (h,l,c out — Ve needs combo)
    gemm_mma<3><<<dim3(4, 4, 1), 128, SMEM_T3, sw>>>(
        wp_hi, wp_lo, 0, wvT_hi, wvT_lo, 0, CC,
        nullptr, 0.f, wpv_hi, wpv_lo, wpv_c, nullptr, CC, 0);
    cudaEventRecord(g_aux.e_wp, sw);

    // per-chunk chains
    for (int c = 0; c < NCHUNK; c++) {
        cudaStream_t st = (c == 0) ? (cudaStream_t)0 : g_aux.sc[c - 1];
        const int b0 = c * CB;
        const size_t oHC = (size_t)b0 * sHC;
        const size_t oSS = (size_t)b0 * sSS;
        const size_t oX = (size_t)b0 * CC * HW;

        gn_stats<<<CB * G, 256, 0, st>>>(x, b0);
        gn_transpose<<<dim3(HW / 32, CC / 32, CB), dim3(32, 8), 0, st>>>(
            x, gn_w, gn_b, b0);

        cudaStreamWaitEvent(st, g_aux.e_wp, 0);

        // Ve[d][j] = Wpv[d]·Ht[j] + (Wp·vb)[d]   (2-MMA compensated)
        gemm2<1><<<dim3(8, 4, CB), 128, SMEM_T3, st>>>(
            wpv_hi, wpv_c, 0, ht_hi + oHC, ht_c + oHC, sHC, CC,
            vbp, nullptr, ve_hi + oHC, ve_c + oHC, nullptr, HW, sHC);
        // T[i][b] = Ht[i]·M2[b] + u[b]   (3-term)
        gemm_mma<0><<<dim3(4, 8, CB), 128, SMEM_T3, st>>>(
            ht_hi + oHC, ht_lo + oHC, sHC, m2_hi, m2_lo, 0, CC,
            u, 0.f, t_hi + oHC, t_lo + oHC, nullptr, nullptr, CC, sHC);
        // S[i][j] = scale * T[i]·Ht[j]   (3-term)
        gemm_mma<2><<<dim3(8, 8, CB), 128, SMEM_T3, st>>>(
            t_hi + oHC, t_lo + oHC, sHC, ht_hi + oHC, ht_lo + oHC, sHC, CC,
            nullptr, scale, nullptr, nullptr, nullptr, s + oSS, HW, sSS);
        softmax_kernel<<<CB * HW, 256, 0, st>>>(s + oSS, p_hi + oSS, p_c + oSS);
        // out[d][i] = x[d][i] + Ve[d]·P[i] + p_b[d]   (2-MMA compensated)
        gemm2<4><<<dim3(8, 4, CB), 128, SMEM_T3, st>>>(
            ve_hi + oHC, ve_c + oHC, sHC, p_hi + oSS, p_c + oSS, sSS, HW,
            p_b, x + oX, nullptr, nullptr, out + oX, HW, sHC);

        if (c > 0) cudaEventRecord(g_aux.e_done[c - 1], st);
    }

    // final join on main stream
    for (int i = 0; i < NCHUNK - 1; i++)
        cudaStreamWaitEvent(0, g_aux.e_done[i], 0);
}